// round 1
// baseline (speedup 1.0000x reference)
#include <cuda_runtime.h>
#include <math.h>

#define BB 4
#define TT 2048
#define CC 1024
#define HH 16
#define DD 64

// Scratch (allocation-free requirement -> __device__ globals)
__device__ float g_qkv[BB * TT * 3 * CC];   // ~100.7 MB
__device__ float g_y[BB * TT * CC];         // ~33.6 MB

// ---------------------------------------------------------------------------
// SGEMM: Out[M,N] = A[M,K] * W[K,N] + bias[N]
// 64x64 block tile, BK=16, 256 threads, 4x4 per-thread microtile.
// ---------------------------------------------------------------------------
__global__ __launch_bounds__(256) void sgemm_bias_kernel(
    const float* __restrict__ A, const float* __restrict__ Wm,
    const float* __restrict__ bias, float* __restrict__ Out,
    int M, int N, int K)
{
    const int BM = 64, BN = 64, BK = 16;
    __shared__ float As[BK][BM];
    __shared__ float Bs[BK][BN];

    int tid = threadIdx.x;
    int tx = tid & 15;        // 0..15 (n dir)
    int ty = tid >> 4;        // 0..15 (m dir)
    int bm = blockIdx.y * BM;
    int bn = blockIdx.x * BN;

    float acc[4][4];
    #pragma unroll
    for (int i = 0; i < 4; i++)
        #pragma unroll
        for (int j = 0; j < 4; j++) acc[i][j] = 0.f;

    for (int k0 = 0; k0 < K; k0 += BK) {
        // A tile: rows bm..bm+63, cols k0..k0+15 -> As[k][m] (transposed)
        {
            int r  = tid >> 2;            // 0..63
            int kc = (tid & 3) << 2;      // 0,4,8,12
            float4 a = *(const float4*)&A[(size_t)(bm + r) * K + k0 + kc];
            As[kc + 0][r] = a.x;
            As[kc + 1][r] = a.y;
            As[kc + 2][r] = a.z;
            As[kc + 3][r] = a.w;
        }
        // B tile: rows k0..k0+15, cols bn..bn+63 -> Bs[k][n]
        {
            int r = tid >> 4;             // 0..15
            int c = (tid & 15) << 2;      // 0..60
            float4 b = *(const float4*)&Wm[(size_t)(k0 + r) * N + bn + c];
            *(float4*)&Bs[r][c] = b;
        }
        __syncthreads();

        #pragma unroll
        for (int kk = 0; kk < BK; kk++) {
            float ra[4], rb[4];
            #pragma unroll
            for (int i = 0; i < 4; i++) ra[i] = As[kk][ty * 4 + i];
            #pragma unroll
            for (int j = 0; j < 4; j++) rb[j] = Bs[kk][tx * 4 + j];
            #pragma unroll
            for (int i = 0; i < 4; i++)
                #pragma unroll
                for (int j = 0; j < 4; j++)
                    acc[i][j] += ra[i] * rb[j];
        }
        __syncthreads();
    }

    #pragma unroll
    for (int i = 0; i < 4; i++) {
        int row = bm + ty * 4 + i;
        #pragma unroll
        for (int j = 0; j < 4; j++) {
            int col = bn + tx * 4 + j;
            Out[(size_t)row * N + col] = acc[i][j] + bias[col];
        }
    }
}

// ---------------------------------------------------------------------------
// Flash-style causal attention (fp32).
// Grid: (T/64, H, B). Block: 64 threads, 1 thread = 1 query row.
// K/V tiles of 64 rows staged in shared memory; online softmax in chunks of
// 16 (fully unrolled -> everything stays in registers).
// ---------------------------------------------------------------------------
__global__ __launch_bounds__(64) void attn_kernel(
    const float* __restrict__ qkv, float* __restrict__ y)
{
    __shared__ float Kt[64][DD];
    __shared__ float Vt[64][DD];

    int tid = threadIdx.x;
    int qt  = blockIdx.x;                 // q tile index 0..31
    int h   = blockIdx.y;
    int b   = blockIdx.z;
    int tq  = qt * 64 + tid;
    const float scale = 0.125f;           // 1/sqrt(64)

    const float* qptr = qkv + (size_t)(b * TT + tq) * (3 * CC) + h * DD;
    float qreg[DD];
    #pragma unroll
    for (int d = 0; d < DD; d += 4) {
        float4 qv = *(const float4*)&qptr[d];
        qreg[d] = qv.x; qreg[d+1] = qv.y; qreg[d+2] = qv.z; qreg[d+3] = qv.w;
    }

    float m = -INFINITY, l = 0.f;
    float acc[DD];
    #pragma unroll
    for (int d = 0; d < DD; d++) acc[d] = 0.f;

    for (int kt = 0; kt <= qt; kt++) {
        int k0 = kt * 64;
        // Cooperative coalesced load of K/V tile: iter r, thread tid -> col tid
        for (int r = 0; r < 64; r++) {
            size_t base = (size_t)(b * TT + k0 + r) * (3 * CC) + h * DD + tid;
            Kt[r][tid] = qkv[base + CC];
            Vt[r][tid] = qkv[base + 2 * CC];
        }
        __syncthreads();

        // Process the 64 keys in 4 chunks of 16 (fully unrolled)
        #pragma unroll 1
        for (int jc = 0; jc < 64; jc += 16) {
            if (k0 + jc > tq) break;      // fully masked from here on

            float s[16];
            float cmax = -INFINITY;
            #pragma unroll
            for (int j = 0; j < 16; j++) {
                int kk = k0 + jc + j;
                if (kk <= tq) {
                    float dot = 0.f;
                    #pragma unroll
                    for (int d = 0; d < DD; d += 4) {
                        float4 kv = *(const float4*)&Kt[jc + j][d];
                        dot += qreg[d]     * kv.x;
                        dot += qreg[d + 1] * kv.y;
                        dot += qreg[d + 2] * kv.z;
                        dot += qreg[d + 3] * kv.w;
                    }
                    s[j] = dot * scale;
                    cmax = fmaxf(cmax, s[j]);
                } else {
                    s[j] = -INFINITY;
                }
            }

            float mnew = fmaxf(m, cmax);
            float alpha = __expf(m - mnew);
            l *= alpha;
            #pragma unroll
            for (int d = 0; d < DD; d++) acc[d] *= alpha;

            #pragma unroll
            for (int j = 0; j < 16; j++) {
                float p = __expf(s[j] - mnew);
                l += p;
                #pragma unroll
                for (int d = 0; d < DD; d += 4) {
                    float4 vv = *(const float4*)&Vt[jc + j][d];
                    acc[d]     += p * vv.x;
                    acc[d + 1] += p * vv.y;
                    acc[d + 2] += p * vv.z;
                    acc[d + 3] += p * vv.w;
                }
            }
            m = mnew;
        }
        __syncthreads();
    }

    float inv = 1.f / l;
    float* yptr = y + (size_t)(b * TT + tq) * CC + h * DD;
    #pragma unroll
    for (int d = 0; d < DD; d += 4) {
        float4 o;
        o.x = acc[d] * inv; o.y = acc[d+1] * inv;
        o.z = acc[d+2] * inv; o.w = acc[d+3] * inv;
        *(float4*)&yptr[d] = o;
    }
}

// ---------------------------------------------------------------------------
extern "C" void kernel_launch(void* const* d_in, const int* in_sizes, int n_in,
                              void* d_out, int out_size)
{
    const float* x      = (const float*)d_in[0];
    const float* w_attn = (const float*)d_in[1];
    const float* b_attn = (const float*)d_in[2];
    const float* w_proj = (const float*)d_in[3];
    const float* b_proj = (const float*)d_in[4];
    float* out = (float*)d_out;

    float* qkv; cudaGetSymbolAddress((void**)&qkv, g_qkv);
    float* y;   cudaGetSymbolAddress((void**)&y,   g_y);

    const int M = BB * TT;        // 8192

    // 1) qkv = x @ w_attn + b_attn   [8192, 3072]
    {
        dim3 grid((3 * CC) / 64, M / 64);
        sgemm_bias_kernel<<<grid, 256>>>(x, w_attn, b_attn, qkv, M, 3 * CC, CC);
    }

    // 2) causal flash attention -> y [8192, 1024]
    {
        dim3 grid(TT / 64, HH, BB);
        attn_kernel<<<grid, 64>>>(qkv, y);
    }

    // 3) out = y @ w_proj + b_proj   [8192, 1024]
    {
        dim3 grid(CC / 64, M / 64);
        sgemm_bias_kernel<<<grid, 256>>>(y, w_proj, b_proj, out, M, CC, CC);
    }
}

// round 2
// speedup vs baseline: 1.3602x; 1.3602x over previous
#include <cuda_runtime.h>
#include <math.h>
#include <stdint.h>

#define BB 4
#define TT 2048
#define CC 1024
#define HH 16
#define DD 64

// Scratch (allocation-free requirement -> __device__ globals)
__device__ float g_qkv[BB * TT * 3 * CC];   // ~100.7 MB
__device__ float g_y[BB * TT * CC];         // ~33.6 MB

// ---------------------------------------------------------------------------
// TF32 helpers
// ---------------------------------------------------------------------------
__device__ __forceinline__ uint32_t f2tf32(float x) {
    uint32_t r;
    asm("cvt.rna.tf32.f32 %0, %1;" : "=r"(r) : "f"(x));
    return r;
}

__device__ __forceinline__ void mma_tf32(float* d, const uint32_t* a,
                                         const uint32_t* b, const float* c) {
    asm volatile(
        "mma.sync.aligned.m16n8k8.row.col.f32.tf32.tf32.f32 "
        "{%0,%1,%2,%3}, {%4,%5,%6,%7}, {%8,%9}, {%10,%11,%12,%13};\n"
        : "=f"(d[0]), "=f"(d[1]), "=f"(d[2]), "=f"(d[3])
        : "r"(a[0]), "r"(a[1]), "r"(a[2]), "r"(a[3]),
          "r"(b[0]), "r"(b[1]),
          "f"(c[0]), "f"(c[1]), "f"(c[2]), "f"(c[3]));
}

// ---------------------------------------------------------------------------
// TF32 GEMM: Out[M,N] = A[M,K] * W[K,N] + bias[N]
// 128x128x32 block tile, 256 threads (8 warps, 4x2 warp grid, 32x64 warp tile)
// ---------------------------------------------------------------------------
#define GPAD 36   // smem row stride (floats); makes frag-gather banks (4m+k)%32 distinct

__global__ __launch_bounds__(256) void gemm_tf32_kernel(
    const float* __restrict__ A, const float* __restrict__ Wm,
    const float* __restrict__ bias, float* __restrict__ Out,
    int M, int N, int K)
{
    __shared__ uint32_t As[128][GPAD];   // [m][k], tf32 bits
    __shared__ uint32_t Bs[128][GPAD];   // [n][k], tf32 bits

    const int tid  = threadIdx.x;
    const int lane = tid & 31;
    const int warp = tid >> 5;
    const int warpM = warp >> 1;   // 0..3
    const int warpN = warp & 1;    // 0..1
    const int bm = blockIdx.y * 128;
    const int bn = blockIdx.x * 128;

    float acc[2][8][4];
    #pragma unroll
    for (int mt = 0; mt < 2; mt++)
        #pragma unroll
        for (int nt = 0; nt < 8; nt++)
            #pragma unroll
            for (int r = 0; r < 4; r++) acc[mt][nt][r] = 0.f;

    // staging index precompute
    const int a_row = tid >> 1;                 // 0..127
    const int a_col = (tid & 1) * 16;           // 0 or 16
    const int b_kr  = tid >> 3;                 // 0..31
    const int b_nc  = (tid & 7) * 16;           // 0..112

    for (int k0 = 0; k0 < K; k0 += 32) {
        // A tile: 128 rows x 32 cols -> As[m][k]
        {
            const float* src = &A[(size_t)(bm + a_row) * K + k0 + a_col];
            #pragma unroll
            for (int i = 0; i < 4; i++) {
                float4 v = *(const float4*)&src[i * 4];
                As[a_row][a_col + i * 4 + 0] = f2tf32(v.x);
                As[a_row][a_col + i * 4 + 1] = f2tf32(v.y);
                As[a_row][a_col + i * 4 + 2] = f2tf32(v.z);
                As[a_row][a_col + i * 4 + 3] = f2tf32(v.w);
            }
        }
        // B tile: 32 rows x 128 cols of W -> Bs[n][k] (transposed)
        {
            const float* src = &Wm[(size_t)(k0 + b_kr) * N + bn + b_nc];
            #pragma unroll
            for (int i = 0; i < 4; i++) {
                float4 v = *(const float4*)&src[i * 4];
                Bs[b_nc + i * 4 + 0][b_kr] = f2tf32(v.x);
                Bs[b_nc + i * 4 + 1][b_kr] = f2tf32(v.y);
                Bs[b_nc + i * 4 + 2][b_kr] = f2tf32(v.z);
                Bs[b_nc + i * 4 + 3][b_kr] = f2tf32(v.w);
            }
        }
        __syncthreads();

        #pragma unroll
        for (int ks = 0; ks < 4; ks++) {
            const int kb = ks * 8;
            uint32_t afr[2][4];
            #pragma unroll
            for (int mt = 0; mt < 2; mt++) {
                int mb = warpM * 32 + mt * 16 + (lane >> 2);
                int kc = kb + (lane & 3);
                afr[mt][0] = As[mb    ][kc];
                afr[mt][1] = As[mb + 8][kc];
                afr[mt][2] = As[mb    ][kc + 4];
                afr[mt][3] = As[mb + 8][kc + 4];
            }
            uint32_t bfr[8][2];
            #pragma unroll
            for (int nt = 0; nt < 8; nt++) {
                int nb = warpN * 64 + nt * 8 + (lane >> 2);
                int kc = kb + (lane & 3);
                bfr[nt][0] = Bs[nb][kc];
                bfr[nt][1] = Bs[nb][kc + 4];
            }
            #pragma unroll
            for (int mt = 0; mt < 2; mt++)
                #pragma unroll
                for (int nt = 0; nt < 8; nt++)
                    mma_tf32(acc[mt][nt], afr[mt], bfr[nt], acc[mt][nt]);
        }
        __syncthreads();
    }

    // Epilogue: bias + store
    #pragma unroll
    for (int mt = 0; mt < 2; mt++) {
        int row0 = bm + warpM * 32 + mt * 16 + (lane >> 2);
        #pragma unroll
        for (int nt = 0; nt < 8; nt++) {
            int col = bn + warpN * 64 + nt * 8 + 2 * (lane & 3);
            float b0 = bias[col], b1 = bias[col + 1];
            Out[(size_t)row0 * N + col]           = acc[mt][nt][0] + b0;
            Out[(size_t)row0 * N + col + 1]       = acc[mt][nt][1] + b1;
            Out[(size_t)(row0 + 8) * N + col]     = acc[mt][nt][2] + b0;
            Out[(size_t)(row0 + 8) * N + col + 1] = acc[mt][nt][3] + b1;
        }
    }
}

// ---------------------------------------------------------------------------
// Flash-style causal attention (fp32).
// Grid: (T/64, H, B). Block: 64 threads, 1 thread = 1 query row.
// Interior tiles take an unmasked fast path; only the diagonal tile masks.
// ---------------------------------------------------------------------------
__global__ __launch_bounds__(64) void attn_kernel(
    const float* __restrict__ qkv, float* __restrict__ y)
{
    __shared__ float Kt[64][DD];
    __shared__ float Vt[64][DD];

    int tid = threadIdx.x;
    int qt  = blockIdx.x;                 // q tile index 0..31
    int h   = blockIdx.y;
    int b   = blockIdx.z;
    int tq  = qt * 64 + tid;
    const float scale = 0.125f;           // 1/sqrt(64)

    const float* qptr = qkv + (size_t)(b * TT + tq) * (3 * CC) + h * DD;
    float qreg[DD];
    #pragma unroll
    for (int d = 0; d < DD; d += 4) {
        float4 qv = *(const float4*)&qptr[d];
        qreg[d] = qv.x; qreg[d+1] = qv.y; qreg[d+2] = qv.z; qreg[d+3] = qv.w;
    }

    float m = -INFINITY, l = 0.f;
    float acc[DD];
    #pragma unroll
    for (int d = 0; d < DD; d++) acc[d] = 0.f;

    for (int kt = 0; kt <= qt; kt++) {
        int k0 = kt * 64;
        for (int r = 0; r < 64; r++) {
            size_t base = (size_t)(b * TT + k0 + r) * (3 * CC) + h * DD + tid;
            Kt[r][tid] = qkv[base + CC];
            Vt[r][tid] = qkv[base + 2 * CC];
        }
        __syncthreads();

        if (kt < qt) {
            // ---------- interior tile: no masking ----------
            #pragma unroll 1
            for (int jc = 0; jc < 64; jc += 16) {
                float s[16];
                float cmax = -INFINITY;
                #pragma unroll
                for (int j = 0; j < 16; j++) {
                    float dot = 0.f;
                    #pragma unroll
                    for (int d = 0; d < DD; d += 4) {
                        float4 kv = *(const float4*)&Kt[jc + j][d];
                        dot += qreg[d]     * kv.x;
                        dot += qreg[d + 1] * kv.y;
                        dot += qreg[d + 2] * kv.z;
                        dot += qreg[d + 3] * kv.w;
                    }
                    s[j] = dot * scale;
                    cmax = fmaxf(cmax, s[j]);
                }
                float mnew = fmaxf(m, cmax);
                float alpha = __expf(m - mnew);
                l *= alpha;
                #pragma unroll
                for (int d = 0; d < DD; d++) acc[d] *= alpha;
                #pragma unroll
                for (int j = 0; j < 16; j++) {
                    float p = __expf(s[j] - mnew);
                    l += p;
                    #pragma unroll
                    for (int d = 0; d < DD; d += 4) {
                        float4 vv = *(const float4*)&Vt[jc + j][d];
                        acc[d]     += p * vv.x;
                        acc[d + 1] += p * vv.y;
                        acc[d + 2] += p * vv.z;
                        acc[d + 3] += p * vv.w;
                    }
                }
                m = mnew;
            }
        } else {
            // ---------- diagonal tile: causal masking ----------
            #pragma unroll 1
            for (int jc = 0; jc < 64; jc += 16) {
                if (k0 + jc > tq) break;
                float s[16];
                float cmax = -INFINITY;
                #pragma unroll
                for (int j = 0; j < 16; j++) {
                    int kk = k0 + jc + j;
                    if (kk <= tq) {
                        float dot = 0.f;
                        #pragma unroll
                        for (int d = 0; d < DD; d += 4) {
                            float4 kv = *(const float4*)&Kt[jc + j][d];
                            dot += qreg[d]     * kv.x;
                            dot += qreg[d + 1] * kv.y;
                            dot += qreg[d + 2] * kv.z;
                            dot += qreg[d + 3] * kv.w;
                        }
                        s[j] = dot * scale;
                        cmax = fmaxf(cmax, s[j]);
                    } else {
                        s[j] = -INFINITY;
                    }
                }
                float mnew = fmaxf(m, cmax);
                float alpha = __expf(m - mnew);
                l *= alpha;
                #pragma unroll
                for (int d = 0; d < DD; d++) acc[d] *= alpha;
                #pragma unroll
                for (int j = 0; j < 16; j++) {
                    float p = __expf(s[j] - mnew);
                    l += p;
                    #pragma unroll
                    for (int d = 0; d < DD; d += 4) {
                        float4 vv = *(const float4*)&Vt[jc + j][d];
                        acc[d]     += p * vv.x;
                        acc[d + 1] += p * vv.y;
                        acc[d + 2] += p * vv.z;
                        acc[d + 3] += p * vv.w;
                    }
                }
                m = mnew;
            }
        }
        __syncthreads();
    }

    float inv = 1.f / l;
    float* yptr = y + (size_t)(b * TT + tq) * CC + h * DD;
    #pragma unroll
    for (int d = 0; d < DD; d += 4) {
        float4 o;
        o.x = acc[d] * inv; o.y = acc[d+1] * inv;
        o.z = acc[d+2] * inv; o.w = acc[d+3] * inv;
        *(float4*)&yptr[d] = o;
    }
}

// ---------------------------------------------------------------------------
extern "C" void kernel_launch(void* const* d_in, const int* in_sizes, int n_in,
                              void* d_out, int out_size)
{
    const float* x      = (const float*)d_in[0];
    const float* w_attn = (const float*)d_in[1];
    const float* b_attn = (const float*)d_in[2];
    const float* w_proj = (const float*)d_in[3];
    const float* b_proj = (const float*)d_in[4];
    float* out = (float*)d_out;

    float* qkv; cudaGetSymbolAddress((void**)&qkv, g_qkv);
    float* y;   cudaGetSymbolAddress((void**)&y,   g_y);

    const int M = BB * TT;        // 8192

    // 1) qkv = x @ w_attn + b_attn   [8192, 3072]
    {
        dim3 grid((3 * CC) / 128, M / 128);
        gemm_tf32_kernel<<<grid, 256>>>(x, w_attn, b_attn, qkv, M, 3 * CC, CC);
    }

    // 2) causal flash attention -> y [8192, 1024]
    {
        dim3 grid(TT / 64, HH, BB);
        attn_kernel<<<grid, 64>>>(qkv, y);
    }

    // 3) out = y @ w_proj + b_proj   [8192, 1024]
    {
        dim3 grid(CC / 128, M / 128);
        gemm_tf32_kernel<<<grid, 256>>>(y, w_proj, b_proj, out, M, CC, CC);
    }
}

// round 5
// speedup vs baseline: 2.5533x; 1.8772x over previous
#include <cuda_runtime.h>
#include <math.h>
#include <stdint.h>

#define BB 4
#define TT 2048
#define CC 1024
#define HH 16
#define DD 64

// Scratch (allocation-free requirement -> __device__ globals)
__device__ float g_qkv[BB * TT * 3 * CC];   // ~100.7 MB
__device__ float g_y[BB * TT * CC];         // ~33.6 MB

// ---------------------------------------------------------------------------
// TF32 helpers
// ---------------------------------------------------------------------------
__device__ __forceinline__ uint32_t f2tf32(float x) {
    uint32_t r;
    asm("cvt.rna.tf32.f32 %0, %1;" : "=r"(r) : "f"(x));
    return r;
}

__device__ __forceinline__ void mma_tf32(float* d, const uint32_t* a,
                                         const uint32_t* b, const float* c) {
    asm volatile(
        "mma.sync.aligned.m16n8k8.row.col.f32.tf32.tf32.f32 "
        "{%0,%1,%2,%3}, {%4,%5,%6,%7}, {%8,%9}, {%10,%11,%12,%13};\n"
        : "=f"(d[0]), "=f"(d[1]), "=f"(d[2]), "=f"(d[3])
        : "r"(a[0]), "r"(a[1]), "r"(a[2]), "r"(a[3]),
          "r"(b[0]), "r"(b[1]),
          "f"(c[0]), "f"(c[1]), "f"(c[2]), "f"(c[3]));
}

// ---------------------------------------------------------------------------
// TF32 GEMM: Out[M,N] = A[M,K] * W[K,N] + bias[N]
// 128x128x32 block tile, 256 threads (8 warps, 4x2 warp grid, 32x64 warp tile)
// ---------------------------------------------------------------------------
#define GPAD 36

__global__ __launch_bounds__(256) void gemm_tf32_kernel(
    const float* __restrict__ A, const float* __restrict__ Wm,
    const float* __restrict__ bias, float* __restrict__ Out,
    int M, int N, int K)
{
    __shared__ uint32_t As[128][GPAD];   // [m][k], tf32 bits
    __shared__ uint32_t Bs[128][GPAD];   // [n][k], tf32 bits

    const int tid  = threadIdx.x;
    const int lane = tid & 31;
    const int warp = tid >> 5;
    const int warpM = warp >> 1;   // 0..3
    const int warpN = warp & 1;    // 0..1
    const int bm = blockIdx.y * 128;
    const int bn = blockIdx.x * 128;

    float acc[2][8][4];
    #pragma unroll
    for (int mt = 0; mt < 2; mt++)
        #pragma unroll
        for (int nt = 0; nt < 8; nt++)
            #pragma unroll
            for (int r = 0; r < 4; r++) acc[mt][nt][r] = 0.f;

    const int a_row = tid >> 1;
    const int a_col = (tid & 1) * 16;
    const int b_kr  = tid >> 3;
    const int b_nc  = (tid & 7) * 16;

    for (int k0 = 0; k0 < K; k0 += 32) {
        {
            const float* src = &A[(size_t)(bm + a_row) * K + k0 + a_col];
            #pragma unroll
            for (int i = 0; i < 4; i++) {
                float4 v = *(const float4*)&src[i * 4];
                As[a_row][a_col + i * 4 + 0] = f2tf32(v.x);
                As[a_row][a_col + i * 4 + 1] = f2tf32(v.y);
                As[a_row][a_col + i * 4 + 2] = f2tf32(v.z);
                As[a_row][a_col + i * 4 + 3] = f2tf32(v.w);
            }
        }
        {
            const float* src = &Wm[(size_t)(k0 + b_kr) * N + bn + b_nc];
            #pragma unroll
            for (int i = 0; i < 4; i++) {
                float4 v = *(const float4*)&src[i * 4];
                Bs[b_nc + i * 4 + 0][b_kr] = f2tf32(v.x);
                Bs[b_nc + i * 4 + 1][b_kr] = f2tf32(v.y);
                Bs[b_nc + i * 4 + 2][b_kr] = f2tf32(v.z);
                Bs[b_nc + i * 4 + 3][b_kr] = f2tf32(v.w);
            }
        }
        __syncthreads();

        #pragma unroll
        for (int ks = 0; ks < 4; ks++) {
            const int kb = ks * 8;
            uint32_t afr[2][4];
            #pragma unroll
            for (int mt = 0; mt < 2; mt++) {
                int mb = warpM * 32 + mt * 16 + (lane >> 2);
                int kc = kb + (lane & 3);
                afr[mt][0] = As[mb    ][kc];
                afr[mt][1] = As[mb + 8][kc];
                afr[mt][2] = As[mb    ][kc + 4];
                afr[mt][3] = As[mb + 8][kc + 4];
            }
            uint32_t bfr[8][2];
            #pragma unroll
            for (int nt = 0; nt < 8; nt++) {
                int nb = warpN * 64 + nt * 8 + (lane >> 2);
                int kc = kb + (lane & 3);
                bfr[nt][0] = Bs[nb][kc];
                bfr[nt][1] = Bs[nb][kc + 4];
            }
            #pragma unroll
            for (int mt = 0; mt < 2; mt++)
                #pragma unroll
                for (int nt = 0; nt < 8; nt++)
                    mma_tf32(acc[mt][nt], afr[mt], bfr[nt], acc[mt][nt]);
        }
        __syncthreads();
    }

    #pragma unroll
    for (int mt = 0; mt < 2; mt++) {
        int row0 = bm + warpM * 32 + mt * 16 + (lane >> 2);
        #pragma unroll
        for (int nt = 0; nt < 8; nt++) {
            int col = bn + warpN * 64 + nt * 8 + 2 * (lane & 3);
            float b0 = bias[col], b1 = bias[col + 1];
            Out[(size_t)row0 * N + col]           = acc[mt][nt][0] + b0;
            Out[(size_t)row0 * N + col + 1]       = acc[mt][nt][1] + b1;
            Out[(size_t)(row0 + 8) * N + col]     = acc[mt][nt][2] + b0;
            Out[(size_t)(row0 + 8) * N + col + 1] = acc[mt][nt][3] + b1;
        }
    }
}

// ---------------------------------------------------------------------------
// TF32 mma flash attention (causal).
// Grid: (T/64, H, B). Block: 128 threads = 4 warps; warp w owns q-rows
// [qt*64 + 16w, +16). Q fragments in registers (scale pre-folded).
// K tile [key][dim], V tile transposed [dim][key], P via smem roundtrip.
// Shared memory is DYNAMIC (52,224 B > 48 KB static limit).
// ---------------------------------------------------------------------------
#define APAD 68
#define ATTN_SMEM_BYTES (3 * 64 * APAD * 4)

__global__ __launch_bounds__(128) void attn_mma_kernel(
    const float* __restrict__ qkv, float* __restrict__ y)
{
    extern __shared__ uint32_t smem_u[];
    uint32_t (*Ks)[APAD] = (uint32_t(*)[APAD])(smem_u);                 // K[key][dim]
    uint32_t (*Vs)[APAD] = (uint32_t(*)[APAD])(smem_u + 64 * APAD);     // V^T[dim][key]
    uint32_t (*Ps)[APAD] = (uint32_t(*)[APAD])(smem_u + 2 * 64 * APAD); // Q stage / P

    const int tid  = threadIdx.x;
    const int lane = tid & 31;
    const int warp = tid >> 5;
    const int qt = blockIdx.x;
    const int h  = blockIdx.y;
    const int b  = blockIdx.z;
    const int q0 = qt * 64;

    const size_t rstride = 3 * CC;
    const float* base = qkv + (size_t)b * TT * rstride + h * DD;

    // ---- Stage Q (scaled) into Ps, then pull fragments into registers ----
    {
        const int r  = tid >> 1;            // 0..63
        const int c0 = (tid & 1) * 32;      // 0 or 32
        const float* src = base + (size_t)(q0 + r) * rstride + c0;
        #pragma unroll
        for (int i = 0; i < 8; i++) {
            float4 v = *(const float4*)&src[i * 4];
            Ps[r][c0 + i * 4 + 0] = f2tf32(v.x * 0.125f);
            Ps[r][c0 + i * 4 + 1] = f2tf32(v.y * 0.125f);
            Ps[r][c0 + i * 4 + 2] = f2tf32(v.z * 0.125f);
            Ps[r][c0 + i * 4 + 3] = f2tf32(v.w * 0.125f);
        }
    }
    __syncthreads();

    uint32_t qf[8][4];
    {
        const int r  = warp * 16 + (lane >> 2);
        #pragma unroll
        for (int kb = 0; kb < 8; kb++) {
            const int kc = kb * 8 + (lane & 3);
            qf[kb][0] = Ps[r    ][kc];
            qf[kb][1] = Ps[r + 8][kc];
            qf[kb][2] = Ps[r    ][kc + 4];
            qf[kb][3] = Ps[r + 8][kc + 4];
        }
    }

    float oacc[8][4];
    #pragma unroll
    for (int nt = 0; nt < 8; nt++)
        #pragma unroll
        for (int r = 0; r < 4; r++) oacc[nt][r] = 0.f;

    float m_a = -1e30f, m_b = -1e30f, l_a = 0.f, l_b = 0.f;

    const int st_r  = tid >> 1;
    const int st_c0 = (tid & 1) * 32;

    for (int kt = 0; kt <= qt; kt++) {
        const int k0 = kt * 64;
        __syncthreads();   // everyone done with previous K/V/P tiles

        // ---- stage K and V^T tiles ----
        {
            const float* srcK = base + (size_t)(k0 + st_r) * rstride + CC     + st_c0;
            const float* srcV = base + (size_t)(k0 + st_r) * rstride + 2 * CC + st_c0;
            #pragma unroll
            for (int i = 0; i < 8; i++) {
                float4 kv = *(const float4*)&srcK[i * 4];
                Ks[st_r][st_c0 + i * 4 + 0] = f2tf32(kv.x);
                Ks[st_r][st_c0 + i * 4 + 1] = f2tf32(kv.y);
                Ks[st_r][st_c0 + i * 4 + 2] = f2tf32(kv.z);
                Ks[st_r][st_c0 + i * 4 + 3] = f2tf32(kv.w);
                float4 vv = *(const float4*)&srcV[i * 4];
                Vs[st_c0 + i * 4 + 0][st_r] = f2tf32(vv.x);
                Vs[st_c0 + i * 4 + 1][st_r] = f2tf32(vv.y);
                Vs[st_c0 + i * 4 + 2][st_r] = f2tf32(vv.z);
                Vs[st_c0 + i * 4 + 3][st_r] = f2tf32(vv.w);
            }
        }
        __syncthreads();

        // ---- S = Q K^T (this warp's 16 rows x 64 keys) ----
        float sacc[8][4];
        #pragma unroll
        for (int nt = 0; nt < 8; nt++) {
            sacc[nt][0] = sacc[nt][1] = sacc[nt][2] = sacc[nt][3] = 0.f;
            const int nb = nt * 8 + (lane >> 2);
            #pragma unroll
            for (int kb = 0; kb < 8; kb++) {
                const int kc = kb * 8 + (lane & 3);
                uint32_t bfr[2];
                bfr[0] = Ks[nb][kc];
                bfr[1] = Ks[nb][kc + 4];
                mma_tf32(sacc[nt], qf[kb], bfr, sacc[nt]);
            }
        }

        // ---- causal mask on diagonal tile ----
        if (kt == qt) {
            const int ra = warp * 16 + (lane >> 2);   // local row (0..63)
            #pragma unroll
            for (int nt = 0; nt < 8; nt++) {
                const int c = nt * 8 + 2 * (lane & 3);
                if (c     > ra)     sacc[nt][0] = -1e30f;
                if (c + 1 > ra)     sacc[nt][1] = -1e30f;
                if (c     > ra + 8) sacc[nt][2] = -1e30f;
                if (c + 1 > ra + 8) sacc[nt][3] = -1e30f;
            }
        }

        // ---- row max (16 vals/thread per row, then quad reduce) ----
        float mx_a = -1e30f, mx_b = -1e30f;
        #pragma unroll
        for (int nt = 0; nt < 8; nt++) {
            mx_a = fmaxf(mx_a, fmaxf(sacc[nt][0], sacc[nt][1]));
            mx_b = fmaxf(mx_b, fmaxf(sacc[nt][2], sacc[nt][3]));
        }
        mx_a = fmaxf(mx_a, __shfl_xor_sync(0xffffffff, mx_a, 1));
        mx_a = fmaxf(mx_a, __shfl_xor_sync(0xffffffff, mx_a, 2));
        mx_b = fmaxf(mx_b, __shfl_xor_sync(0xffffffff, mx_b, 1));
        mx_b = fmaxf(mx_b, __shfl_xor_sync(0xffffffff, mx_b, 2));

        const float mnew_a = fmaxf(m_a, mx_a);
        const float mnew_b = fmaxf(m_b, mx_b);
        const float alpha_a = __expf(m_a - mnew_a);
        const float alpha_b = __expf(m_b - mnew_b);
        l_a *= alpha_a;
        l_b *= alpha_b;
        #pragma unroll
        for (int nt = 0; nt < 8; nt++) {
            oacc[nt][0] *= alpha_a; oacc[nt][1] *= alpha_a;
            oacc[nt][2] *= alpha_b; oacc[nt][3] *= alpha_b;
        }
        m_a = mnew_a; m_b = mnew_b;

        // ---- P = exp(S - m), accumulate l, store tf32 P to smem ----
        {
            const int pr = warp * 16 + (lane >> 2);
            #pragma unroll
            for (int nt = 0; nt < 8; nt++) {
                const int pc = nt * 8 + 2 * (lane & 3);
                float p0 = __expf(sacc[nt][0] - mnew_a);
                float p1 = __expf(sacc[nt][1] - mnew_a);
                float p2 = __expf(sacc[nt][2] - mnew_b);
                float p3 = __expf(sacc[nt][3] - mnew_b);
                l_a += p0 + p1;
                l_b += p2 + p3;
                Ps[pr    ][pc]     = f2tf32(p0);
                Ps[pr    ][pc + 1] = f2tf32(p1);
                Ps[pr + 8][pc]     = f2tf32(p2);
                Ps[pr + 8][pc + 1] = f2tf32(p3);
            }
        }
        __syncwarp();

        // ---- O += P V ----
        {
            const int pr = warp * 16 + (lane >> 2);
            #pragma unroll
            for (int kb = 0; kb < 8; kb++) {
                const int kc = kb * 8 + (lane & 3);
                uint32_t pf[4];
                pf[0] = Ps[pr    ][kc];
                pf[1] = Ps[pr + 8][kc];
                pf[2] = Ps[pr    ][kc + 4];
                pf[3] = Ps[pr + 8][kc + 4];
                #pragma unroll
                for (int nt = 0; nt < 8; nt++) {
                    const int db = nt * 8 + (lane >> 2);
                    uint32_t bfr[2];
                    bfr[0] = Vs[db][kc];
                    bfr[1] = Vs[db][kc + 4];
                    mma_tf32(oacc[nt], pf, bfr, oacc[nt]);
                }
            }
        }
    }

    // ---- reduce l across the quad (each thread summed 16 of 64 columns) ----
    l_a += __shfl_xor_sync(0xffffffff, l_a, 1);
    l_a += __shfl_xor_sync(0xffffffff, l_a, 2);
    l_b += __shfl_xor_sync(0xffffffff, l_b, 1);
    l_b += __shfl_xor_sync(0xffffffff, l_b, 2);

    // ---- epilogue: normalize and write y ----
    const float inv_a = 1.f / l_a;
    const float inv_b = 1.f / l_b;
    const int row_a = q0 + warp * 16 + (lane >> 2);
    float* ybase = y + (size_t)b * TT * CC + (size_t)h * DD;
    #pragma unroll
    for (int nt = 0; nt < 8; nt++) {
        const int d = nt * 8 + 2 * (lane & 3);
        float2 va, vb;
        va.x = oacc[nt][0] * inv_a; va.y = oacc[nt][1] * inv_a;
        vb.x = oacc[nt][2] * inv_b; vb.y = oacc[nt][3] * inv_b;
        *(float2*)&ybase[(size_t)row_a * CC + d]       = va;
        *(float2*)&ybase[(size_t)(row_a + 8) * CC + d] = vb;
    }
}

// ---------------------------------------------------------------------------
extern "C" void kernel_launch(void* const* d_in, const int* in_sizes, int n_in,
                              void* d_out, int out_size)
{
    const float* x      = (const float*)d_in[0];
    const float* w_attn = (const float*)d_in[1];
    const float* b_attn = (const float*)d_in[2];
    const float* w_proj = (const float*)d_in[3];
    const float* b_proj = (const float*)d_in[4];
    float* out = (float*)d_out;

    float* qkv; cudaGetSymbolAddress((void**)&qkv, g_qkv);
    float* y;   cudaGetSymbolAddress((void**)&y,   g_y);

    // opt-in to >48KB dynamic smem for the attention kernel (idempotent)
    cudaFuncSetAttribute(attn_mma_kernel,
                         cudaFuncAttributeMaxDynamicSharedMemorySize,
                         ATTN_SMEM_BYTES);

    const int M = BB * TT;        // 8192

    // 1) qkv = x @ w_attn + b_attn   [8192, 3072]
    {
        dim3 grid((3 * CC) / 128, M / 128);
        gemm_tf32_kernel<<<grid, 256>>>(x, w_attn, b_attn, qkv, M, 3 * CC, CC);
    }

    // 2) causal flash attention (tf32 mma) -> y [8192, 1024]
    {
        dim3 grid(TT / 64, HH, BB);
        attn_mma_kernel<<<grid, 128, ATTN_SMEM_BYTES>>>(qkv, y);
    }

    // 3) out = y @ w_proj + b_proj   [8192, 1024]
    {
        dim3 grid(CC / 128, M / 128);
        gemm_tf32_kernel<<<grid, 256>>>(y, w_proj, b_proj, out, M, CC, CC);
    }
}

// round 6
// speedup vs baseline: 2.8876x; 1.1310x over previous
#include <cuda_runtime.h>
#include <math.h>
#include <stdint.h>

#define BB 4
#define TT 2048
#define CC 1024
#define HH 16
#define DD 64

// Scratch (allocation-free requirement -> __device__ globals)
__device__ float g_qkv[BB * TT * 3 * CC];   // ~100.7 MB
__device__ float g_y[BB * TT * CC];         // ~33.6 MB

// ---------------------------------------------------------------------------
// TF32 helpers
// ---------------------------------------------------------------------------
__device__ __forceinline__ uint32_t f2tf32(float x) {
    uint32_t r;
    asm("cvt.rna.tf32.f32 %0, %1;" : "=r"(r) : "f"(x));
    return r;
}

__device__ __forceinline__ void mma_tf32(float* d, const uint32_t* a,
                                         const uint32_t* b, const float* c) {
    asm volatile(
        "mma.sync.aligned.m16n8k8.row.col.f32.tf32.tf32.f32 "
        "{%0,%1,%2,%3}, {%4,%5,%6,%7}, {%8,%9}, {%10,%11,%12,%13};\n"
        : "=f"(d[0]), "=f"(d[1]), "=f"(d[2]), "=f"(d[3])
        : "r"(a[0]), "r"(a[1]), "r"(a[2]), "r"(a[3]),
          "r"(b[0]), "r"(b[1]),
          "f"(c[0]), "f"(c[1]), "f"(c[2]), "f"(c[3]));
}

__device__ __forceinline__ uint32_t smem_u32addr(const void* p) {
    return (uint32_t)__cvta_generic_to_shared(p);
}

__device__ __forceinline__ void cp_async16(uint32_t dst, const void* src) {
    asm volatile("cp.async.cg.shared.global [%0], [%1], 16;\n"
                 :: "r"(dst), "l"(src));
}
__device__ __forceinline__ void cp_async_commit() {
    asm volatile("cp.async.commit_group;\n");
}
__device__ __forceinline__ void cp_async_wait_all() {
    asm volatile("cp.async.wait_group 0;\n");
}

// ---------------------------------------------------------------------------
// TF32 GEMM: Out[M,N] = A[M,K] * W[K,N] + bias[N]
// 128x128x32 tile, 256 threads. Double-buffered smem pipeline:
//   A: GMEM->regs prefetch, cvt->STS (tf32, [m][k], stride 36)
//   B: cp.async raw fp32 ([k][n], stride 136 -> conflict-free frag loads),
//      cvt at fragment load.
// ---------------------------------------------------------------------------
#define GPAD 36
#define BPAD 136
#define A_BUF_U32 (128 * GPAD)            // 4608
#define B_BUF_F32 (32 * BPAD)             // 4352
#define GEMM_SMEM_BYTES ((2 * A_BUF_U32 + 2 * B_BUF_F32) * 4)   // 71680

__global__ __launch_bounds__(256, 2) void gemm_tf32_kernel(
    const float* __restrict__ A, const float* __restrict__ Wm,
    const float* __restrict__ bias, float* __restrict__ Out,
    int M, int N, int K)
{
    extern __shared__ uint32_t dynsmem[];
    uint32_t* Asb[2] = { dynsmem, dynsmem + A_BUF_U32 };
    float*    Bsb[2] = { (float*)(dynsmem + 2 * A_BUF_U32),
                         (float*)(dynsmem + 2 * A_BUF_U32) + B_BUF_F32 };

    const int tid  = threadIdx.x;
    const int lane = tid & 31;
    const int warp = tid >> 5;
    const int warpM = warp >> 1;   // 0..3
    const int warpN = warp & 1;    // 0..1
    const int bm = blockIdx.y * 128;
    const int bn = blockIdx.x * 128;

    float acc[2][8][4];
    #pragma unroll
    for (int mt = 0; mt < 2; mt++)
        #pragma unroll
        for (int nt = 0; nt < 8; nt++)
            #pragma unroll
            for (int r = 0; r < 4; r++) acc[mt][nt][r] = 0.f;

    // A staging geometry
    const int a_row = tid >> 1;                 // 0..127
    const int a_col = (tid & 1) * 16;           // 0 or 16
    const float* aSrcBase = &A[(size_t)(bm + a_row) * K + a_col];

    // B cp.async geometry: 1024 float4s per tile, 4 per thread
    // chunk j: f4idx = j*256 + tid; row = f4idx>>5 (0..31); col4 = f4idx&31
    const int nIters = K / 32;

    // ---- prologue: A0 -> regs, B0 -> cp.async buf0 ----
    float4 aPre[4];
    #pragma unroll
    for (int i = 0; i < 4; i++)
        aPre[i] = *(const float4*)&aSrcBase[i * 4];

    {
        float* Bp = Bsb[0];
        #pragma unroll
        for (int j = 0; j < 4; j++) {
            int f4 = j * 256 + tid;
            int row = f4 >> 5, col4 = f4 & 31;
            cp_async16(smem_u32addr(&Bp[row * BPAD + col4 * 4]),
                       &Wm[(size_t)row * N + bn + col4 * 4]);
        }
        cp_async_commit();
    }

    int p = 0;
    for (int it = 0; it < nIters; it++) {
        // ---- STS A_it (convert to tf32) into buffer p ----
        {
            uint32_t* Ap = Asb[p];
            #pragma unroll
            for (int i = 0; i < 4; i++) {
                Ap[a_row * GPAD + a_col + i * 4 + 0] = f2tf32(aPre[i].x);
                Ap[a_row * GPAD + a_col + i * 4 + 1] = f2tf32(aPre[i].y);
                Ap[a_row * GPAD + a_col + i * 4 + 2] = f2tf32(aPre[i].z);
                Ap[a_row * GPAD + a_col + i * 4 + 3] = f2tf32(aPre[i].w);
            }
        }
        cp_async_wait_all();      // B_it landed
        __syncthreads();

        // ---- prefetch next tile ----
        if (it + 1 < nIters) {
            const int k0n = (it + 1) * 32;
            #pragma unroll
            for (int i = 0; i < 4; i++)
                aPre[i] = *(const float4*)&aSrcBase[k0n + i * 4];
            float* Bp = Bsb[p ^ 1];
            #pragma unroll
            for (int j = 0; j < 4; j++) {
                int f4 = j * 256 + tid;
                int row = f4 >> 5, col4 = f4 & 31;
                cp_async16(smem_u32addr(&Bp[row * BPAD + col4 * 4]),
                           &Wm[(size_t)(k0n + row) * N + bn + col4 * 4]);
            }
            cp_async_commit();
        }

        // ---- MMA on buffers p ----
        {
            const uint32_t* Ap = Asb[p];
            const float*    Bp = Bsb[p];
            #pragma unroll
            for (int ks = 0; ks < 4; ks++) {
                const int kb = ks * 8;
                uint32_t afr[2][4];
                #pragma unroll
                for (int mt = 0; mt < 2; mt++) {
                    int mb = warpM * 32 + mt * 16 + (lane >> 2);
                    int kc = kb + (lane & 3);
                    afr[mt][0] = Ap[mb * GPAD + kc];
                    afr[mt][1] = Ap[(mb + 8) * GPAD + kc];
                    afr[mt][2] = Ap[mb * GPAD + kc + 4];
                    afr[mt][3] = Ap[(mb + 8) * GPAD + kc + 4];
                }
                uint32_t bfr[8][2];
                #pragma unroll
                for (int nt = 0; nt < 8; nt++) {
                    int nb = warpN * 64 + nt * 8 + (lane >> 2);
                    int kc = kb + (lane & 3);
                    bfr[nt][0] = f2tf32(Bp[kc * BPAD + nb]);
                    bfr[nt][1] = f2tf32(Bp[(kc + 4) * BPAD + nb]);
                }
                #pragma unroll
                for (int mt = 0; mt < 2; mt++)
                    #pragma unroll
                    for (int nt = 0; nt < 8; nt++)
                        mma_tf32(acc[mt][nt], afr[mt], bfr[nt], acc[mt][nt]);
            }
        }
        p ^= 1;
    }

    // ---- epilogue: bias + store ----
    #pragma unroll
    for (int mt = 0; mt < 2; mt++) {
        int row0 = bm + warpM * 32 + mt * 16 + (lane >> 2);
        #pragma unroll
        for (int nt = 0; nt < 8; nt++) {
            int col = bn + warpN * 64 + nt * 8 + 2 * (lane & 3);
            float b0 = bias[col], b1 = bias[col + 1];
            Out[(size_t)row0 * N + col]           = acc[mt][nt][0] + b0;
            Out[(size_t)row0 * N + col + 1]       = acc[mt][nt][1] + b1;
            Out[(size_t)(row0 + 8) * N + col]     = acc[mt][nt][2] + b0;
            Out[(size_t)(row0 + 8) * N + col + 1] = acc[mt][nt][3] + b1;
        }
    }
}

// ---------------------------------------------------------------------------
// TF32 mma flash attention (causal) — unchanged from R5 (passing).
// ---------------------------------------------------------------------------
#define APAD 68
#define ATTN_SMEM_BYTES (3 * 64 * APAD * 4)

__global__ __launch_bounds__(128) void attn_mma_kernel(
    const float* __restrict__ qkv, float* __restrict__ y)
{
    extern __shared__ uint32_t smem_u[];
    uint32_t (*Ks)[APAD] = (uint32_t(*)[APAD])(smem_u);
    uint32_t (*Vs)[APAD] = (uint32_t(*)[APAD])(smem_u + 64 * APAD);
    uint32_t (*Ps)[APAD] = (uint32_t(*)[APAD])(smem_u + 2 * 64 * APAD);

    const int tid  = threadIdx.x;
    const int lane = tid & 31;
    const int warp = tid >> 5;
    const int qt = blockIdx.x;
    const int h  = blockIdx.y;
    const int b  = blockIdx.z;
    const int q0 = qt * 64;

    const size_t rstride = 3 * CC;
    const float* base = qkv + (size_t)b * TT * rstride + h * DD;

    {
        const int r  = tid >> 1;
        const int c0 = (tid & 1) * 32;
        const float* src = base + (size_t)(q0 + r) * rstride + c0;
        #pragma unroll
        for (int i = 0; i < 8; i++) {
            float4 v = *(const float4*)&src[i * 4];
            Ps[r][c0 + i * 4 + 0] = f2tf32(v.x * 0.125f);
            Ps[r][c0 + i * 4 + 1] = f2tf32(v.y * 0.125f);
            Ps[r][c0 + i * 4 + 2] = f2tf32(v.z * 0.125f);
            Ps[r][c0 + i * 4 + 3] = f2tf32(v.w * 0.125f);
        }
    }
    __syncthreads();

    uint32_t qf[8][4];
    {
        const int r  = warp * 16 + (lane >> 2);
        #pragma unroll
        for (int kb = 0; kb < 8; kb++) {
            const int kc = kb * 8 + (lane & 3);
            qf[kb][0] = Ps[r    ][kc];
            qf[kb][1] = Ps[r + 8][kc];
            qf[kb][2] = Ps[r    ][kc + 4];
            qf[kb][3] = Ps[r + 8][kc + 4];
        }
    }

    float oacc[8][4];
    #pragma unroll
    for (int nt = 0; nt < 8; nt++)
        #pragma unroll
        for (int r = 0; r < 4; r++) oacc[nt][r] = 0.f;

    float m_a = -1e30f, m_b = -1e30f, l_a = 0.f, l_b = 0.f;

    const int st_r  = tid >> 1;
    const int st_c0 = (tid & 1) * 32;

    for (int kt = 0; kt <= qt; kt++) {
        const int k0 = kt * 64;
        __syncthreads();

        {
            const float* srcK = base + (size_t)(k0 + st_r) * rstride + CC     + st_c0;
            const float* srcV = base + (size_t)(k0 + st_r) * rstride + 2 * CC + st_c0;
            #pragma unroll
            for (int i = 0; i < 8; i++) {
                float4 kv = *(const float4*)&srcK[i * 4];
                Ks[st_r][st_c0 + i * 4 + 0] = f2tf32(kv.x);
                Ks[st_r][st_c0 + i * 4 + 1] = f2tf32(kv.y);
                Ks[st_r][st_c0 + i * 4 + 2] = f2tf32(kv.z);
                Ks[st_r][st_c0 + i * 4 + 3] = f2tf32(kv.w);
                float4 vv = *(const float4*)&srcV[i * 4];
                Vs[st_c0 + i * 4 + 0][st_r] = f2tf32(vv.x);
                Vs[st_c0 + i * 4 + 1][st_r] = f2tf32(vv.y);
                Vs[st_c0 + i * 4 + 2][st_r] = f2tf32(vv.z);
                Vs[st_c0 + i * 4 + 3][st_r] = f2tf32(vv.w);
            }
        }
        __syncthreads();

        float sacc[8][4];
        #pragma unroll
        for (int nt = 0; nt < 8; nt++) {
            sacc[nt][0] = sacc[nt][1] = sacc[nt][2] = sacc[nt][3] = 0.f;
            const int nb = nt * 8 + (lane >> 2);
            #pragma unroll
            for (int kb = 0; kb < 8; kb++) {
                const int kc = kb * 8 + (lane & 3);
                uint32_t bfr[2];
                bfr[0] = Ks[nb][kc];
                bfr[1] = Ks[nb][kc + 4];
                mma_tf32(sacc[nt], qf[kb], bfr, sacc[nt]);
            }
        }

        if (kt == qt) {
            const int ra = warp * 16 + (lane >> 2);
            #pragma unroll
            for (int nt = 0; nt < 8; nt++) {
                const int c = nt * 8 + 2 * (lane & 3);
                if (c     > ra)     sacc[nt][0] = -1e30f;
                if (c + 1 > ra)     sacc[nt][1] = -1e30f;
                if (c     > ra + 8) sacc[nt][2] = -1e30f;
                if (c + 1 > ra + 8) sacc[nt][3] = -1e30f;
            }
        }

        float mx_a = -1e30f, mx_b = -1e30f;
        #pragma unroll
        for (int nt = 0; nt < 8; nt++) {
            mx_a = fmaxf(mx_a, fmaxf(sacc[nt][0], sacc[nt][1]));
            mx_b = fmaxf(mx_b, fmaxf(sacc[nt][2], sacc[nt][3]));
        }
        mx_a = fmaxf(mx_a, __shfl_xor_sync(0xffffffff, mx_a, 1));
        mx_a = fmaxf(mx_a, __shfl_xor_sync(0xffffffff, mx_a, 2));
        mx_b = fmaxf(mx_b, __shfl_xor_sync(0xffffffff, mx_b, 1));
        mx_b = fmaxf(mx_b, __shfl_xor_sync(0xffffffff, mx_b, 2));

        const float mnew_a = fmaxf(m_a, mx_a);
        const float mnew_b = fmaxf(m_b, mx_b);
        const float alpha_a = __expf(m_a - mnew_a);
        const float alpha_b = __expf(m_b - mnew_b);
        l_a *= alpha_a;
        l_b *= alpha_b;
        #pragma unroll
        for (int nt = 0; nt < 8; nt++) {
            oacc[nt][0] *= alpha_a; oacc[nt][1] *= alpha_a;
            oacc[nt][2] *= alpha_b; oacc[nt][3] *= alpha_b;
        }
        m_a = mnew_a; m_b = mnew_b;

        {
            const int pr = warp * 16 + (lane >> 2);
            #pragma unroll
            for (int nt = 0; nt < 8; nt++) {
                const int pc = nt * 8 + 2 * (lane & 3);
                float p0 = __expf(sacc[nt][0] - mnew_a);
                float p1 = __expf(sacc[nt][1] - mnew_a);
                float p2 = __expf(sacc[nt][2] - mnew_b);
                float p3 = __expf(sacc[nt][3] - mnew_b);
                l_a += p0 + p1;
                l_b += p2 + p3;
                Ps[pr    ][pc]     = f2tf32(p0);
                Ps[pr    ][pc + 1] = f2tf32(p1);
                Ps[pr + 8][pc]     = f2tf32(p2);
                Ps[pr + 8][pc + 1] = f2tf32(p3);
            }
        }
        __syncwarp();

        {
            const int pr = warp * 16 + (lane >> 2);
            #pragma unroll
            for (int kb = 0; kb < 8; kb++) {
                const int kc = kb * 8 + (lane & 3);
                uint32_t pf[4];
                pf[0] = Ps[pr    ][kc];
                pf[1] = Ps[pr + 8][kc];
                pf[2] = Ps[pr    ][kc + 4];
                pf[3] = Ps[pr + 8][kc + 4];
                #pragma unroll
                for (int nt = 0; nt < 8; nt++) {
                    const int db = nt * 8 + (lane >> 2);
                    uint32_t bfr[2];
                    bfr[0] = Vs[db][kc];
                    bfr[1] = Vs[db][kc + 4];
                    mma_tf32(oacc[nt], pf, bfr, oacc[nt]);
                }
            }
        }
    }

    l_a += __shfl_xor_sync(0xffffffff, l_a, 1);
    l_a += __shfl_xor_sync(0xffffffff, l_a, 2);
    l_b += __shfl_xor_sync(0xffffffff, l_b, 1);
    l_b += __shfl_xor_sync(0xffffffff, l_b, 2);

    const float inv_a = 1.f / l_a;
    const float inv_b = 1.f / l_b;
    const int row_a = q0 + warp * 16 + (lane >> 2);
    float* ybase = y + (size_t)b * TT * CC + (size_t)h * DD;
    #pragma unroll
    for (int nt = 0; nt < 8; nt++) {
        const int d = nt * 8 + 2 * (lane & 3);
        float2 va, vb;
        va.x = oacc[nt][0] * inv_a; va.y = oacc[nt][1] * inv_a;
        vb.x = oacc[nt][2] * inv_b; vb.y = oacc[nt][3] * inv_b;
        *(float2*)&ybase[(size_t)row_a * CC + d]       = va;
        *(float2*)&ybase[(size_t)(row_a + 8) * CC + d] = vb;
    }
}

// ---------------------------------------------------------------------------
extern "C" void kernel_launch(void* const* d_in, const int* in_sizes, int n_in,
                              void* d_out, int out_size)
{
    const float* x      = (const float*)d_in[0];
    const float* w_attn = (const float*)d_in[1];
    const float* b_attn = (const float*)d_in[2];
    const float* w_proj = (const float*)d_in[3];
    const float* b_proj = (const float*)d_in[4];
    float* out = (float*)d_out;

    float* qkv; cudaGetSymbolAddress((void**)&qkv, g_qkv);
    float* y;   cudaGetSymbolAddress((void**)&y,   g_y);

    cudaFuncSetAttribute(gemm_tf32_kernel,
                         cudaFuncAttributeMaxDynamicSharedMemorySize,
                         GEMM_SMEM_BYTES);
    cudaFuncSetAttribute(attn_mma_kernel,
                         cudaFuncAttributeMaxDynamicSharedMemorySize,
                         ATTN_SMEM_BYTES);

    const int M = BB * TT;        // 8192

    // 1) qkv = x @ w_attn + b_attn   [8192, 3072]
    {
        dim3 grid((3 * CC) / 128, M / 128);
        gemm_tf32_kernel<<<grid, 256, GEMM_SMEM_BYTES>>>(x, w_attn, b_attn, qkv, M, 3 * CC, CC);
    }

    // 2) causal flash attention (tf32 mma) -> y [8192, 1024]
    {
        dim3 grid(TT / 64, HH, BB);
        attn_mma_kernel<<<grid, 128, ATTN_SMEM_BYTES>>>(qkv, y);
    }

    // 3) out = y @ w_proj + b_proj   [8192, 1024]
    {
        dim3 grid(CC / 128, M / 128);
        gemm_tf32_kernel<<<grid, 256, GEMM_SMEM_BYTES>>>(y, w_proj, b_proj, out, M, CC, CC);
    }
}

// round 7
// speedup vs baseline: 3.5130x; 1.2166x over previous
#include <cuda_runtime.h>
#include <math.h>
#include <stdint.h>

#define BB 4
#define TT 2048
#define CC 1024
#define HH 16
#define DD 64

// Scratch (allocation-free requirement -> __device__ globals)
__device__ float g_qkv[BB * TT * 3 * CC];   // ~100.7 MB
__device__ float g_y[BB * TT * CC];         // ~33.6 MB

// ---------------------------------------------------------------------------
// TF32 helpers
// ---------------------------------------------------------------------------
__device__ __forceinline__ uint32_t f2tf32(float x) {
    uint32_t r;
    asm("cvt.rna.tf32.f32 %0, %1;" : "=r"(r) : "f"(x));
    return r;
}

__device__ __forceinline__ void mma_tf32(float* d, const uint32_t* a,
                                         const uint32_t* b, const float* c) {
    asm volatile(
        "mma.sync.aligned.m16n8k8.row.col.f32.tf32.tf32.f32 "
        "{%0,%1,%2,%3}, {%4,%5,%6,%7}, {%8,%9}, {%10,%11,%12,%13};\n"
        : "=f"(d[0]), "=f"(d[1]), "=f"(d[2]), "=f"(d[3])
        : "r"(a[0]), "r"(a[1]), "r"(a[2]), "r"(a[3]),
          "r"(b[0]), "r"(b[1]),
          "f"(c[0]), "f"(c[1]), "f"(c[2]), "f"(c[3]));
}

__device__ __forceinline__ uint32_t smem_u32addr(const void* p) {
    return (uint32_t)__cvta_generic_to_shared(p);
}

__device__ __forceinline__ void cp_async16(uint32_t dst, const void* src) {
    asm volatile("cp.async.cg.shared.global [%0], [%1], 16;\n"
                 :: "r"(dst), "l"(src));
}
__device__ __forceinline__ void cp_async_commit() {
    asm volatile("cp.async.commit_group;\n");
}
__device__ __forceinline__ void cp_async_wait_all() {
    asm volatile("cp.async.wait_group 0;\n");
}

// ---------------------------------------------------------------------------
// TF32 GEMM: Out[M,N] = A[M,K] * W[K,N] + bias[N]   (unchanged from R6)
// ---------------------------------------------------------------------------
#define GPAD 36
#define BPAD 136
#define A_BUF_U32 (128 * GPAD)
#define B_BUF_F32 (32 * BPAD)
#define GEMM_SMEM_BYTES ((2 * A_BUF_U32 + 2 * B_BUF_F32) * 4)

__global__ __launch_bounds__(256, 2) void gemm_tf32_kernel(
    const float* __restrict__ A, const float* __restrict__ Wm,
    const float* __restrict__ bias, float* __restrict__ Out,
    int M, int N, int K)
{
    extern __shared__ uint32_t dynsmem[];
    uint32_t* Asb[2] = { dynsmem, dynsmem + A_BUF_U32 };
    float*    Bsb[2] = { (float*)(dynsmem + 2 * A_BUF_U32),
                         (float*)(dynsmem + 2 * A_BUF_U32) + B_BUF_F32 };

    const int tid  = threadIdx.x;
    const int lane = tid & 31;
    const int warp = tid >> 5;
    const int warpM = warp >> 1;
    const int warpN = warp & 1;
    const int bm = blockIdx.y * 128;
    const int bn = blockIdx.x * 128;

    float acc[2][8][4];
    #pragma unroll
    for (int mt = 0; mt < 2; mt++)
        #pragma unroll
        for (int nt = 0; nt < 8; nt++)
            #pragma unroll
            for (int r = 0; r < 4; r++) acc[mt][nt][r] = 0.f;

    const int a_row = tid >> 1;
    const int a_col = (tid & 1) * 16;
    const float* aSrcBase = &A[(size_t)(bm + a_row) * K + a_col];
    const int nIters = K / 32;

    float4 aPre[4];
    #pragma unroll
    for (int i = 0; i < 4; i++)
        aPre[i] = *(const float4*)&aSrcBase[i * 4];

    {
        float* Bp = Bsb[0];
        #pragma unroll
        for (int j = 0; j < 4; j++) {
            int f4 = j * 256 + tid;
            int row = f4 >> 5, col4 = f4 & 31;
            cp_async16(smem_u32addr(&Bp[row * BPAD + col4 * 4]),
                       &Wm[(size_t)row * N + bn + col4 * 4]);
        }
        cp_async_commit();
    }

    int p = 0;
    for (int it = 0; it < nIters; it++) {
        {
            uint32_t* Ap = Asb[p];
            #pragma unroll
            for (int i = 0; i < 4; i++) {
                Ap[a_row * GPAD + a_col + i * 4 + 0] = f2tf32(aPre[i].x);
                Ap[a_row * GPAD + a_col + i * 4 + 1] = f2tf32(aPre[i].y);
                Ap[a_row * GPAD + a_col + i * 4 + 2] = f2tf32(aPre[i].z);
                Ap[a_row * GPAD + a_col + i * 4 + 3] = f2tf32(aPre[i].w);
            }
        }
        cp_async_wait_all();
        __syncthreads();

        if (it + 1 < nIters) {
            const int k0n = (it + 1) * 32;
            #pragma unroll
            for (int i = 0; i < 4; i++)
                aPre[i] = *(const float4*)&aSrcBase[k0n + i * 4];
            float* Bp = Bsb[p ^ 1];
            #pragma unroll
            for (int j = 0; j < 4; j++) {
                int f4 = j * 256 + tid;
                int row = f4 >> 5, col4 = f4 & 31;
                cp_async16(smem_u32addr(&Bp[row * BPAD + col4 * 4]),
                           &Wm[(size_t)(k0n + row) * N + bn + col4 * 4]);
            }
            cp_async_commit();
        }

        {
            const uint32_t* Ap = Asb[p];
            const float*    Bp = Bsb[p];
            #pragma unroll
            for (int ks = 0; ks < 4; ks++) {
                const int kb = ks * 8;
                uint32_t afr[2][4];
                #pragma unroll
                for (int mt = 0; mt < 2; mt++) {
                    int mb = warpM * 32 + mt * 16 + (lane >> 2);
                    int kc = kb + (lane & 3);
                    afr[mt][0] = Ap[mb * GPAD + kc];
                    afr[mt][1] = Ap[(mb + 8) * GPAD + kc];
                    afr[mt][2] = Ap[mb * GPAD + kc + 4];
                    afr[mt][3] = Ap[(mb + 8) * GPAD + kc + 4];
                }
                uint32_t bfr[8][2];
                #pragma unroll
                for (int nt = 0; nt < 8; nt++) {
                    int nb = warpN * 64 + nt * 8 + (lane >> 2);
                    int kc = kb + (lane & 3);
                    bfr[nt][0] = f2tf32(Bp[kc * BPAD + nb]);
                    bfr[nt][1] = f2tf32(Bp[(kc + 4) * BPAD + nb]);
                }
                #pragma unroll
                for (int mt = 0; mt < 2; mt++)
                    #pragma unroll
                    for (int nt = 0; nt < 8; nt++)
                        mma_tf32(acc[mt][nt], afr[mt], bfr[nt], acc[mt][nt]);
            }
        }
        p ^= 1;
    }

    #pragma unroll
    for (int mt = 0; mt < 2; mt++) {
        int row0 = bm + warpM * 32 + mt * 16 + (lane >> 2);
        #pragma unroll
        for (int nt = 0; nt < 8; nt++) {
            int col = bn + warpN * 64 + nt * 8 + 2 * (lane & 3);
            float b0 = bias[col], b1 = bias[col + 1];
            Out[(size_t)row0 * N + col]           = acc[mt][nt][0] + b0;
            Out[(size_t)row0 * N + col + 1]       = acc[mt][nt][1] + b1;
            Out[(size_t)(row0 + 8) * N + col]     = acc[mt][nt][2] + b0;
            Out[(size_t)(row0 + 8) * N + col + 1] = acc[mt][nt][3] + b1;
        }
    }
}

// ---------------------------------------------------------------------------
// TF32 mma flash attention v2 (causal).
// Grid: (T/128, H, B). Block: 256 threads = 8 warps; warp w owns q-rows
// [qt*128 + 16w, +16). K/V tiles (64 keys) cp.async'd raw fp32,
// double-buffered; V kept row-major (no transpose needed for PV mma).
// K pad 68 (bank 4q+r), V pad 72 (bank 8r+q) -> conflict-free gathers.
// ---------------------------------------------------------------------------
#define KPAD 68
#define VPAD 72
#define KBUF_U32 (64 * KPAD)              // 4352
#define VBUF_U32 (64 * VPAD)              // 4608
#define P_U32    (128 * KPAD)             // 8704
#define ATTN_SMEM_BYTES ((2 * KBUF_U32 + 2 * VBUF_U32 + P_U32) * 4)  // 106496

__global__ __launch_bounds__(256) void attn_mma_kernel(
    const float* __restrict__ qkv, float* __restrict__ y)
{
    extern __shared__ uint32_t smem_u[];
    float* Kb[2] = { (float*)smem_u, (float*)(smem_u + KBUF_U32) };
    float* Vb[2] = { (float*)(smem_u + 2 * KBUF_U32),
                     (float*)(smem_u + 2 * KBUF_U32 + VBUF_U32) };
    uint32_t* Pst = smem_u + 2 * KBUF_U32 + 2 * VBUF_U32;   // [128][KPAD]

    const int tid  = threadIdx.x;
    const int lane = tid & 31;
    const int warp = tid >> 5;
    const int qt = blockIdx.x;            // 0..15 (128-row q tiles)
    const int h  = blockIdx.y;
    const int b  = blockIdx.z;
    const int q0 = qt * 128;

    const size_t rstride = 3 * CC;
    const float* base = qkv + (size_t)b * TT * rstride + h * DD;

    // ---- Stage Q (scaled, tf32) into Pst, pull fragments into registers ----
    {
        const int r  = tid >> 1;            // 0..127
        const int c0 = (tid & 1) * 32;
        const float* src = base + (size_t)(q0 + r) * rstride + c0;
        #pragma unroll
        for (int i = 0; i < 8; i++) {
            float4 v = *(const float4*)&src[i * 4];
            Pst[r * KPAD + c0 + i * 4 + 0] = f2tf32(v.x * 0.125f);
            Pst[r * KPAD + c0 + i * 4 + 1] = f2tf32(v.y * 0.125f);
            Pst[r * KPAD + c0 + i * 4 + 2] = f2tf32(v.z * 0.125f);
            Pst[r * KPAD + c0 + i * 4 + 3] = f2tf32(v.w * 0.125f);
        }
    }
    __syncthreads();

    uint32_t qf[8][4];
    {
        const int r = warp * 16 + (lane >> 2);
        #pragma unroll
        for (int kb = 0; kb < 8; kb++) {
            const int kc = kb * 8 + (lane & 3);
            qf[kb][0] = Pst[r * KPAD + kc];
            qf[kb][1] = Pst[(r + 8) * KPAD + kc];
            qf[kb][2] = Pst[r * KPAD + kc + 4];
            qf[kb][3] = Pst[(r + 8) * KPAD + kc + 4];
        }
    }

    float oacc[8][4];
    #pragma unroll
    for (int nt = 0; nt < 8; nt++)
        #pragma unroll
        for (int r = 0; r < 4; r++) oacc[nt][r] = 0.f;

    float m_a = -1e30f, m_b = -1e30f, l_a = 0.f, l_b = 0.f;

    const int nk = 2 * qt + 2;            // number of 64-key tiles

    // staging geometry: 1024 float4 per K tile (and per V tile), 4/thread
    // f4 = j*256 + tid; row = f4>>4 (0..63); c4 = f4&15
    // ---- prologue: tile 0 ----
    {
        const float* srcK = base + CC;
        const float* srcV = base + 2 * CC;
        #pragma unroll
        for (int j = 0; j < 4; j++) {
            int f4 = j * 256 + tid;
            int row = f4 >> 4, c4 = f4 & 15;
            cp_async16(smem_u32addr(&Kb[0][row * KPAD + c4 * 4]),
                       srcK + (size_t)row * rstride + c4 * 4);
            cp_async16(smem_u32addr(&Vb[0][row * VPAD + c4 * 4]),
                       srcV + (size_t)row * rstride + c4 * 4);
        }
        cp_async_commit();
    }

    int p = 0;
    for (int kt = 0; kt < nk; kt++) {
        const int k0 = kt * 64;
        cp_async_wait_all();
        __syncthreads();   // tile kt visible; all warps done with buffer p^1

        // ---- prefetch tile kt+1 into p^1 ----
        if (kt + 1 < nk) {
            const size_t r0 = (size_t)(kt + 1) * 64;
            const float* srcK = base + CC;
            const float* srcV = base + 2 * CC;
            float* Kp = Kb[p ^ 1];
            float* Vp = Vb[p ^ 1];
            #pragma unroll
            for (int j = 0; j < 4; j++) {
                int f4 = j * 256 + tid;
                int row = f4 >> 4, c4 = f4 & 15;
                cp_async16(smem_u32addr(&Kp[row * KPAD + c4 * 4]),
                           srcK + (r0 + row) * rstride + c4 * 4);
                cp_async16(smem_u32addr(&Vp[row * VPAD + c4 * 4]),
                           srcV + (r0 + row) * rstride + c4 * 4);
            }
            cp_async_commit();
        }

        const float* Kp = Kb[p];
        const float* Vp = Vb[p];

        // ---- S = Q K^T (16 rows x 64 keys per warp) ----
        float sacc[8][4];
        #pragma unroll
        for (int nt = 0; nt < 8; nt++) {
            sacc[nt][0] = sacc[nt][1] = sacc[nt][2] = sacc[nt][3] = 0.f;
            const int nb = nt * 8 + (lane >> 2);
            #pragma unroll
            for (int kb = 0; kb < 8; kb++) {
                const int kc = kb * 8 + (lane & 3);
                uint32_t bfr[2];
                bfr[0] = f2tf32(Kp[nb * KPAD + kc]);
                bfr[1] = f2tf32(Kp[nb * KPAD + kc + 4]);
                mma_tf32(sacc[nt], qf[kb], bfr, sacc[nt]);
            }
        }

        // ---- causal mask (only the two diagonal-adjacent tiles) ----
        if (kt >= 2 * qt) {
            const int ra = q0 + warp * 16 + (lane >> 2);   // global row
            #pragma unroll
            for (int nt = 0; nt < 8; nt++) {
                const int c = k0 + nt * 8 + 2 * (lane & 3); // global col
                if (c     > ra)     sacc[nt][0] = -1e30f;
                if (c + 1 > ra)     sacc[nt][1] = -1e30f;
                if (c     > ra + 8) sacc[nt][2] = -1e30f;
                if (c + 1 > ra + 8) sacc[nt][3] = -1e30f;
            }
        }

        // ---- online softmax ----
        float mx_a = -1e30f, mx_b = -1e30f;
        #pragma unroll
        for (int nt = 0; nt < 8; nt++) {
            mx_a = fmaxf(mx_a, fmaxf(sacc[nt][0], sacc[nt][1]));
            mx_b = fmaxf(mx_b, fmaxf(sacc[nt][2], sacc[nt][3]));
        }
        mx_a = fmaxf(mx_a, __shfl_xor_sync(0xffffffff, mx_a, 1));
        mx_a = fmaxf(mx_a, __shfl_xor_sync(0xffffffff, mx_a, 2));
        mx_b = fmaxf(mx_b, __shfl_xor_sync(0xffffffff, mx_b, 1));
        mx_b = fmaxf(mx_b, __shfl_xor_sync(0xffffffff, mx_b, 2));

        const float mnew_a = fmaxf(m_a, mx_a);
        const float mnew_b = fmaxf(m_b, mx_b);
        const float alpha_a = __expf(m_a - mnew_a);
        const float alpha_b = __expf(m_b - mnew_b);
        l_a *= alpha_a;
        l_b *= alpha_b;
        #pragma unroll
        for (int nt = 0; nt < 8; nt++) {
            oacc[nt][0] *= alpha_a; oacc[nt][1] *= alpha_a;
            oacc[nt][2] *= alpha_b; oacc[nt][3] *= alpha_b;
        }
        m_a = mnew_a; m_b = mnew_b;

        // ---- P = exp(S-m) -> smem (tf32), accumulate l ----
        {
            const int pr = warp * 16 + (lane >> 2);
            #pragma unroll
            for (int nt = 0; nt < 8; nt++) {
                const int pc = nt * 8 + 2 * (lane & 3);
                float p0 = __expf(sacc[nt][0] - mnew_a);
                float p1 = __expf(sacc[nt][1] - mnew_a);
                float p2 = __expf(sacc[nt][2] - mnew_b);
                float p3 = __expf(sacc[nt][3] - mnew_b);
                l_a += p0 + p1;
                l_b += p2 + p3;
                Pst[pr * KPAD + pc]           = f2tf32(p0);
                Pst[pr * KPAD + pc + 1]       = f2tf32(p1);
                Pst[(pr + 8) * KPAD + pc]     = f2tf32(p2);
                Pst[(pr + 8) * KPAD + pc + 1] = f2tf32(p3);
            }
        }
        __syncwarp();

        // ---- O += P V   (B[k][n] = V[key][dim], raw row-major) ----
        {
            const int pr = warp * 16 + (lane >> 2);
            #pragma unroll
            for (int kb = 0; kb < 8; kb++) {
                const int kc = kb * 8 + (lane & 3);
                uint32_t pf[4];
                pf[0] = Pst[pr * KPAD + kc];
                pf[1] = Pst[(pr + 8) * KPAD + kc];
                pf[2] = Pst[pr * KPAD + kc + 4];
                pf[3] = Pst[(pr + 8) * KPAD + kc + 4];
                #pragma unroll
                for (int nt = 0; nt < 8; nt++) {
                    const int db = nt * 8 + (lane >> 2);
                    uint32_t bfr[2];
                    bfr[0] = f2tf32(Vp[kc * VPAD + db]);
                    bfr[1] = f2tf32(Vp[(kc + 4) * VPAD + db]);
                    mma_tf32(oacc[nt], pf, bfr, oacc[nt]);
                }
            }
        }
        p ^= 1;
    }

    // ---- reduce l across the quad ----
    l_a += __shfl_xor_sync(0xffffffff, l_a, 1);
    l_a += __shfl_xor_sync(0xffffffff, l_a, 2);
    l_b += __shfl_xor_sync(0xffffffff, l_b, 1);
    l_b += __shfl_xor_sync(0xffffffff, l_b, 2);

    // ---- epilogue ----
    const float inv_a = 1.f / l_a;
    const float inv_b = 1.f / l_b;
    const int row_a = q0 + warp * 16 + (lane >> 2);
    float* ybase = y + (size_t)b * TT * CC + (size_t)h * DD;
    #pragma unroll
    for (int nt = 0; nt < 8; nt++) {
        const int d = nt * 8 + 2 * (lane & 3);
        float2 va, vb;
        va.x = oacc[nt][0] * inv_a; va.y = oacc[nt][1] * inv_a;
        vb.x = oacc[nt][2] * inv_b; vb.y = oacc[nt][3] * inv_b;
        *(float2*)&ybase[(size_t)row_a * CC + d]       = va;
        *(float2*)&ybase[(size_t)(row_a + 8) * CC + d] = vb;
    }
}

// ---------------------------------------------------------------------------
extern "C" void kernel_launch(void* const* d_in, const int* in_sizes, int n_in,
                              void* d_out, int out_size)
{
    const float* x      = (const float*)d_in[0];
    const float* w_attn = (const float*)d_in[1];
    const float* b_attn = (const float*)d_in[2];
    const float* w_proj = (const float*)d_in[3];
    const float* b_proj = (const float*)d_in[4];
    float* out = (float*)d_out;

    float* qkv; cudaGetSymbolAddress((void**)&qkv, g_qkv);
    float* y;   cudaGetSymbolAddress((void**)&y,   g_y);

    cudaFuncSetAttribute(gemm_tf32_kernel,
                         cudaFuncAttributeMaxDynamicSharedMemorySize,
                         GEMM_SMEM_BYTES);
    cudaFuncSetAttribute(attn_mma_kernel,
                         cudaFuncAttributeMaxDynamicSharedMemorySize,
                         ATTN_SMEM_BYTES);

    const int M = BB * TT;        // 8192

    // 1) qkv = x @ w_attn + b_attn   [8192, 3072]
    {
        dim3 grid((3 * CC) / 128, M / 128);
        gemm_tf32_kernel<<<grid, 256, GEMM_SMEM_BYTES>>>(x, w_attn, b_attn, qkv, M, 3 * CC, CC);
    }

    // 2) causal flash attention (tf32 mma, 128-row q tiles) -> y
    {
        dim3 grid(TT / 128, HH, BB);
        attn_mma_kernel<<<grid, 256, ATTN_SMEM_BYTES>>>(qkv, y);
    }

    // 3) out = y @ w_proj + b_proj   [8192, 1024]
    {
        dim3 grid(CC / 128, M / 128);
        gemm_tf32_kernel<<<grid, 256, GEMM_SMEM_BYTES>>>(y, w_proj, b_proj, out, M, CC, CC);
    }
}

// round 8
// speedup vs baseline: 4.2955x; 1.2227x over previous
#include <cuda_runtime.h>
#include <math.h>
#include <stdint.h>

#define BB 4
#define TT 2048
#define CC 1024
#define HH 16
#define DD 64

// Scratch (allocation-free requirement -> __device__ globals)
__device__ float g_qkv[BB * TT * 3 * CC];   // ~100.7 MB
__device__ float g_y[BB * TT * CC];         // ~33.6 MB

// ---------------------------------------------------------------------------
// TF32 / mma / ldmatrix helpers
// ---------------------------------------------------------------------------
__device__ __forceinline__ uint32_t f2tf32(float x) {
    uint32_t r;
    asm("cvt.rna.tf32.f32 %0, %1;" : "=r"(r) : "f"(x));
    return r;
}

__device__ __forceinline__ void mma_tf32(float* d, const uint32_t* a,
                                         const uint32_t* b, const float* c) {
    asm volatile(
        "mma.sync.aligned.m16n8k8.row.col.f32.tf32.tf32.f32 "
        "{%0,%1,%2,%3}, {%4,%5,%6,%7}, {%8,%9}, {%10,%11,%12,%13};\n"
        : "=f"(d[0]), "=f"(d[1]), "=f"(d[2]), "=f"(d[3])
        : "r"(a[0]), "r"(a[1]), "r"(a[2]), "r"(a[3]),
          "r"(b[0]), "r"(b[1]),
          "f"(c[0]), "f"(c[1]), "f"(c[2]), "f"(c[3]));
}

__device__ __forceinline__ uint32_t smem_u32addr(const void* p) {
    return (uint32_t)__cvta_generic_to_shared(p);
}

__device__ __forceinline__ void ldmatrix_x4(uint32_t& d0, uint32_t& d1,
                                            uint32_t& d2, uint32_t& d3,
                                            uint32_t addr) {
    asm volatile("ldmatrix.sync.aligned.m8n8.x4.shared.b16 {%0,%1,%2,%3}, [%4];\n"
                 : "=r"(d0), "=r"(d1), "=r"(d2), "=r"(d3) : "r"(addr));
}

__device__ __forceinline__ void cp_async16(uint32_t dst, const void* src) {
    asm volatile("cp.async.cg.shared.global [%0], [%1], 16;\n"
                 :: "r"(dst), "l"(src));
}
__device__ __forceinline__ void cp_async_commit() {
    asm volatile("cp.async.commit_group;\n");
}
__device__ __forceinline__ void cp_async_wait_all() {
    asm volatile("cp.async.wait_group 0;\n");
}

// ---------------------------------------------------------------------------
// TF32 GEMM v3: Out[M,N] = A[M,K] * W[K,N] + bias[N]
// 128x128x32 tile, 256 threads (8 warps, 4x2, 32x64 warp tile).
//   A: cp.async raw fp32 [m][k] pad36; ldmatrix.x4 frags; cvt on frag regs.
//   B: LDG (coalesced columns) + cvt -> STS.128 tf32 [n][k] pad36;
//      ldmatrix.x4 frags (2 n8-tiles per instr), no frag cvt.
// ---------------------------------------------------------------------------
#define GP 36
#define G_ABUF (128 * GP)      // u32 per A buffer
#define G_BBUF (128 * GP)      // u32 per B buffer
#define GEMM_SMEM_BYTES ((2 * G_ABUF + 2 * G_BBUF) * 4)   // 73728

__global__ __launch_bounds__(256, 2) void gemm_tf32_kernel(
    const float* __restrict__ A, const float* __restrict__ Wm,
    const float* __restrict__ bias, float* __restrict__ Out,
    int M, int N, int K)
{
    extern __shared__ uint32_t dynsmem[];
    uint32_t* Asb[2] = { dynsmem, dynsmem + G_ABUF };
    uint32_t* Bsb[2] = { dynsmem + 2 * G_ABUF, dynsmem + 2 * G_ABUF + G_BBUF };

    const int tid  = threadIdx.x;
    const int lane = tid & 31;
    const int warp = tid >> 5;
    const int warpM = warp >> 1;   // 0..3
    const int warpN = warp & 1;    // 0..1
    const int bm = blockIdx.y * 128;
    const int bn = blockIdx.x * 128;

    float acc[2][8][4];
    #pragma unroll
    for (int mt = 0; mt < 2; mt++)
        #pragma unroll
        for (int nt = 0; nt < 8; nt++)
            #pragma unroll
            for (int r = 0; r < 4; r++) acc[mt][nt][r] = 0.f;

    const int nIters = K / 32;

    // B staging geometry: thread -> one n column, half of k
    const int b_n  = tid & 127;          // 0..127
    const int b_kh = (tid >> 7) * 16;    // 0 or 16
    const float* bSrc = &Wm[(size_t)b_kh * N + bn + b_n];

    // A cp.async geometry: f4 = j*256+tid; row=f4>>3 (0..127), c4=f4&7
    // LDSM addresses (precompute per-thread)
    const int a_ldsm_r = lane & 15;
    const int a_ldsm_c = (lane >> 4) << 2;            // 0 or 4
    const int b_ldsm_r = (lane & 7) + ((lane & 16) ? 8 : 0);
    const int b_ldsm_c = (lane & 8) ? 4 : 0;

    // ---- prologue ----
    {
        uint32_t* Ap = Asb[0];
        #pragma unroll
        for (int j = 0; j < 4; j++) {
            int f4 = j * 256 + tid;
            int row = f4 >> 3, c4 = f4 & 7;
            cp_async16(smem_u32addr(&Ap[row * GP + c4 * 4]),
                       &A[(size_t)(bm + row) * K + c4 * 4]);
        }
        cp_async_commit();
    }
    uint32_t bPre[16];
    #pragma unroll
    for (int i = 0; i < 16; i++)
        bPre[i] = f2tf32(bSrc[(size_t)i * N]);

    int p = 0;
    for (int it = 0; it < nIters; it++) {
        // ---- STS B_it (tf32, [n][k]) into buffer p ----
        {
            uint32_t* Bp = Bsb[p];
            #pragma unroll
            for (int j = 0; j < 4; j++) {
                uint4 v = make_uint4(bPre[4*j], bPre[4*j+1], bPre[4*j+2], bPre[4*j+3]);
                *(uint4*)&Bp[b_n * GP + b_kh + 4 * j] = v;
            }
        }
        cp_async_wait_all();      // A_it landed
        __syncthreads();

        // ---- prefetch next tile ----
        if (it + 1 < nIters) {
            const int k0n = (it + 1) * 32;
            uint32_t* Ap = Asb[p ^ 1];
            #pragma unroll
            for (int j = 0; j < 4; j++) {
                int f4 = j * 256 + tid;
                int row = f4 >> 3, c4 = f4 & 7;
                cp_async16(smem_u32addr(&Ap[row * GP + c4 * 4]),
                           &A[(size_t)(bm + row) * K + k0n + c4 * 4]);
            }
            cp_async_commit();
            #pragma unroll
            for (int i = 0; i < 16; i++)
                bPre[i] = f2tf32(bSrc[(size_t)(k0n + i) * N]);
        }

        // ---- MMA on buffers p ----
        {
            const uint32_t* Ap = Asb[p];
            const uint32_t* Bp = Bsb[p];
            #pragma unroll
            for (int ks = 0; ks < 4; ks++) {
                const int kb = ks * 8;
                uint32_t afr[2][4];
                #pragma unroll
                for (int mt = 0; mt < 2; mt++) {
                    const int mb = warpM * 32 + mt * 16;
                    uint32_t a0, a1, a2, a3;
                    ldmatrix_x4(a0, a1, a2, a3,
                        smem_u32addr(&Ap[(mb + a_ldsm_r) * GP + kb + a_ldsm_c]));
                    afr[mt][0] = f2tf32(__uint_as_float(a0));
                    afr[mt][1] = f2tf32(__uint_as_float(a1));
                    afr[mt][2] = f2tf32(__uint_as_float(a2));
                    afr[mt][3] = f2tf32(__uint_as_float(a3));
                }
                uint32_t bfr[8][2];
                #pragma unroll
                for (int pr = 0; pr < 4; pr++) {
                    const int nb = warpN * 64 + pr * 16;
                    uint32_t d0, d1, d2, d3;
                    ldmatrix_x4(d0, d1, d2, d3,
                        smem_u32addr(&Bp[(nb + b_ldsm_r) * GP + kb + b_ldsm_c]));
                    bfr[2*pr][0]   = d0; bfr[2*pr][1]   = d1;
                    bfr[2*pr+1][0] = d2; bfr[2*pr+1][1] = d3;
                }
                #pragma unroll
                for (int mt = 0; mt < 2; mt++)
                    #pragma unroll
                    for (int nt = 0; nt < 8; nt++)
                        mma_tf32(acc[mt][nt], afr[mt], bfr[nt], acc[mt][nt]);
            }
        }
        p ^= 1;
    }

    // ---- epilogue: bias + store ----
    #pragma unroll
    for (int mt = 0; mt < 2; mt++) {
        int row0 = bm + warpM * 32 + mt * 16 + (lane >> 2);
        #pragma unroll
        for (int nt = 0; nt < 8; nt++) {
            int col = bn + warpN * 64 + nt * 8 + 2 * (lane & 3);
            float b0 = bias[col], b1 = bias[col + 1];
            Out[(size_t)row0 * N + col]           = acc[mt][nt][0] + b0;
            Out[(size_t)row0 * N + col + 1]       = acc[mt][nt][1] + b1;
            Out[(size_t)(row0 + 8) * N + col]     = acc[mt][nt][2] + b0;
            Out[(size_t)(row0 + 8) * N + col + 1] = acc[mt][nt][3] + b1;
        }
    }
}

// ---------------------------------------------------------------------------
// TF32 mma flash attention v2 (causal) — unchanged from R7 (passing).
// ---------------------------------------------------------------------------
#define KPAD 68
#define VPAD 72
#define KBUF_U32 (64 * KPAD)
#define VBUF_U32 (64 * VPAD)
#define P_U32    (128 * KPAD)
#define ATTN_SMEM_BYTES ((2 * KBUF_U32 + 2 * VBUF_U32 + P_U32) * 4)

__global__ __launch_bounds__(256) void attn_mma_kernel(
    const float* __restrict__ qkv, float* __restrict__ y)
{
    extern __shared__ uint32_t smem_u[];
    float* Kb[2] = { (float*)smem_u, (float*)(smem_u + KBUF_U32) };
    float* Vb[2] = { (float*)(smem_u + 2 * KBUF_U32),
                     (float*)(smem_u + 2 * KBUF_U32 + VBUF_U32) };
    uint32_t* Pst = smem_u + 2 * KBUF_U32 + 2 * VBUF_U32;

    const int tid  = threadIdx.x;
    const int lane = tid & 31;
    const int warp = tid >> 5;
    const int qt = blockIdx.x;
    const int h  = blockIdx.y;
    const int b  = blockIdx.z;
    const int q0 = qt * 128;

    const size_t rstride = 3 * CC;
    const float* base = qkv + (size_t)b * TT * rstride + h * DD;

    {
        const int r  = tid >> 1;
        const int c0 = (tid & 1) * 32;
        const float* src = base + (size_t)(q0 + r) * rstride + c0;
        #pragma unroll
        for (int i = 0; i < 8; i++) {
            float4 v = *(const float4*)&src[i * 4];
            Pst[r * KPAD + c0 + i * 4 + 0] = f2tf32(v.x * 0.125f);
            Pst[r * KPAD + c0 + i * 4 + 1] = f2tf32(v.y * 0.125f);
            Pst[r * KPAD + c0 + i * 4 + 2] = f2tf32(v.z * 0.125f);
            Pst[r * KPAD + c0 + i * 4 + 3] = f2tf32(v.w * 0.125f);
        }
    }
    __syncthreads();

    uint32_t qf[8][4];
    {
        const int r = warp * 16 + (lane >> 2);
        #pragma unroll
        for (int kb = 0; kb < 8; kb++) {
            const int kc = kb * 8 + (lane & 3);
            qf[kb][0] = Pst[r * KPAD + kc];
            qf[kb][1] = Pst[(r + 8) * KPAD + kc];
            qf[kb][2] = Pst[r * KPAD + kc + 4];
            qf[kb][3] = Pst[(r + 8) * KPAD + kc + 4];
        }
    }

    float oacc[8][4];
    #pragma unroll
    for (int nt = 0; nt < 8; nt++)
        #pragma unroll
        for (int r = 0; r < 4; r++) oacc[nt][r] = 0.f;

    float m_a = -1e30f, m_b = -1e30f, l_a = 0.f, l_b = 0.f;

    const int nk = 2 * qt + 2;

    {
        const float* srcK = base + CC;
        const float* srcV = base + 2 * CC;
        #pragma unroll
        for (int j = 0; j < 4; j++) {
            int f4 = j * 256 + tid;
            int row = f4 >> 4, c4 = f4 & 15;
            cp_async16(smem_u32addr(&Kb[0][row * KPAD + c4 * 4]),
                       srcK + (size_t)row * rstride + c4 * 4);
            cp_async16(smem_u32addr(&Vb[0][row * VPAD + c4 * 4]),
                       srcV + (size_t)row * rstride + c4 * 4);
        }
        cp_async_commit();
    }

    int p = 0;
    for (int kt = 0; kt < nk; kt++) {
        const int k0 = kt * 64;
        cp_async_wait_all();
        __syncthreads();

        if (kt + 1 < nk) {
            const size_t r0 = (size_t)(kt + 1) * 64;
            const float* srcK = base + CC;
            const float* srcV = base + 2 * CC;
            float* Kp = Kb[p ^ 1];
            float* Vp = Vb[p ^ 1];
            #pragma unroll
            for (int j = 0; j < 4; j++) {
                int f4 = j * 256 + tid;
                int row = f4 >> 4, c4 = f4 & 15;
                cp_async16(smem_u32addr(&Kp[row * KPAD + c4 * 4]),
                           srcK + (r0 + row) * rstride + c4 * 4);
                cp_async16(smem_u32addr(&Vp[row * VPAD + c4 * 4]),
                           srcV + (r0 + row) * rstride + c4 * 4);
            }
            cp_async_commit();
        }

        const float* Kp = Kb[p];
        const float* Vp = Vb[p];

        float sacc[8][4];
        #pragma unroll
        for (int nt = 0; nt < 8; nt++) {
            sacc[nt][0] = sacc[nt][1] = sacc[nt][2] = sacc[nt][3] = 0.f;
            const int nb = nt * 8 + (lane >> 2);
            #pragma unroll
            for (int kb = 0; kb < 8; kb++) {
                const int kc = kb * 8 + (lane & 3);
                uint32_t bfr[2];
                bfr[0] = f2tf32(Kp[nb * KPAD + kc]);
                bfr[1] = f2tf32(Kp[nb * KPAD + kc + 4]);
                mma_tf32(sacc[nt], qf[kb], bfr, sacc[nt]);
            }
        }

        if (kt >= 2 * qt) {
            const int ra = q0 + warp * 16 + (lane >> 2);
            #pragma unroll
            for (int nt = 0; nt < 8; nt++) {
                const int c = k0 + nt * 8 + 2 * (lane & 3);
                if (c     > ra)     sacc[nt][0] = -1e30f;
                if (c + 1 > ra)     sacc[nt][1] = -1e30f;
                if (c     > ra + 8) sacc[nt][2] = -1e30f;
                if (c + 1 > ra + 8) sacc[nt][3] = -1e30f;
            }
        }

        float mx_a = -1e30f, mx_b = -1e30f;
        #pragma unroll
        for (int nt = 0; nt < 8; nt++) {
            mx_a = fmaxf(mx_a, fmaxf(sacc[nt][0], sacc[nt][1]));
            mx_b = fmaxf(mx_b, fmaxf(sacc[nt][2], sacc[nt][3]));
        }
        mx_a = fmaxf(mx_a, __shfl_xor_sync(0xffffffff, mx_a, 1));
        mx_a = fmaxf(mx_a, __shfl_xor_sync(0xffffffff, mx_a, 2));
        mx_b = fmaxf(mx_b, __shfl_xor_sync(0xffffffff, mx_b, 1));
        mx_b = fmaxf(mx_b, __shfl_xor_sync(0xffffffff, mx_b, 2));

        const float mnew_a = fmaxf(m_a, mx_a);
        const float mnew_b = fmaxf(m_b, mx_b);
        const float alpha_a = __expf(m_a - mnew_a);
        const float alpha_b = __expf(m_b - mnew_b);
        l_a *= alpha_a;
        l_b *= alpha_b;
        #pragma unroll
        for (int nt = 0; nt < 8; nt++) {
            oacc[nt][0] *= alpha_a; oacc[nt][1] *= alpha_a;
            oacc[nt][2] *= alpha_b; oacc[nt][3] *= alpha_b;
        }
        m_a = mnew_a; m_b = mnew_b;

        {
            const int pr = warp * 16 + (lane >> 2);
            #pragma unroll
            for (int nt = 0; nt < 8; nt++) {
                const int pc = nt * 8 + 2 * (lane & 3);
                float p0 = __expf(sacc[nt][0] - mnew_a);
                float p1 = __expf(sacc[nt][1] - mnew_a);
                float p2 = __expf(sacc[nt][2] - mnew_b);
                float p3 = __expf(sacc[nt][3] - mnew_b);
                l_a += p0 + p1;
                l_b += p2 + p3;
                Pst[pr * KPAD + pc]           = f2tf32(p0);
                Pst[pr * KPAD + pc + 1]       = f2tf32(p1);
                Pst[(pr + 8) * KPAD + pc]     = f2tf32(p2);
                Pst[(pr + 8) * KPAD + pc + 1] = f2tf32(p3);
            }
        }
        __syncwarp();

        {
            const int pr = warp * 16 + (lane >> 2);
            #pragma unroll
            for (int kb = 0; kb < 8; kb++) {
                const int kc = kb * 8 + (lane & 3);
                uint32_t pf[4];
                pf[0] = Pst[pr * KPAD + kc];
                pf[1] = Pst[(pr + 8) * KPAD + kc];
                pf[2] = Pst[pr * KPAD + kc + 4];
                pf[3] = Pst[(pr + 8) * KPAD + kc + 4];
                #pragma unroll
                for (int nt = 0; nt < 8; nt++) {
                    const int db = nt * 8 + (lane >> 2);
                    uint32_t bfr[2];
                    bfr[0] = f2tf32(Vp[kc * VPAD + db]);
                    bfr[1] = f2tf32(Vp[(kc + 4) * VPAD + db]);
                    mma_tf32(oacc[nt], pf, bfr, oacc[nt]);
                }
            }
        }
        p ^= 1;
    }

    l_a += __shfl_xor_sync(0xffffffff, l_a, 1);
    l_a += __shfl_xor_sync(0xffffffff, l_a, 2);
    l_b += __shfl_xor_sync(0xffffffff, l_b, 1);
    l_b += __shfl_xor_sync(0xffffffff, l_b, 2);

    const float inv_a = 1.f / l_a;
    const float inv_b = 1.f / l_b;
    const int row_a = q0 + warp * 16 + (lane >> 2);
    float* ybase = y + (size_t)b * TT * CC + (size_t)h * DD;
    #pragma unroll
    for (int nt = 0; nt < 8; nt++) {
        const int d = nt * 8 + 2 * (lane & 3);
        float2 va, vb;
        va.x = oacc[nt][0] * inv_a; va.y = oacc[nt][1] * inv_a;
        vb.x = oacc[nt][2] * inv_b; vb.y = oacc[nt][3] * inv_b;
        *(float2*)&ybase[(size_t)row_a * CC + d]       = va;
        *(float2*)&ybase[(size_t)(row_a + 8) * CC + d] = vb;
    }
}

// ---------------------------------------------------------------------------
extern "C" void kernel_launch(void* const* d_in, const int* in_sizes, int n_in,
                              void* d_out, int out_size)
{
    const float* x      = (const float*)d_in[0];
    const float* w_attn = (const float*)d_in[1];
    const float* b_attn = (const float*)d_in[2];
    const float* w_proj = (const float*)d_in[3];
    const float* b_proj = (const float*)d_in[4];
    float* out = (float*)d_out;

    float* qkv; cudaGetSymbolAddress((void**)&qkv, g_qkv);
    float* y;   cudaGetSymbolAddress((void**)&y,   g_y);

    cudaFuncSetAttribute(gemm_tf32_kernel,
                         cudaFuncAttributeMaxDynamicSharedMemorySize,
                         GEMM_SMEM_BYTES);
    cudaFuncSetAttribute(attn_mma_kernel,
                         cudaFuncAttributeMaxDynamicSharedMemorySize,
                         ATTN_SMEM_BYTES);

    const int M = BB * TT;        // 8192

    // 1) qkv = x @ w_attn + b_attn   [8192, 3072]
    {
        dim3 grid((3 * CC) / 128, M / 128);
        gemm_tf32_kernel<<<grid, 256, GEMM_SMEM_BYTES>>>(x, w_attn, b_attn, qkv, M, 3 * CC, CC);
    }

    // 2) causal flash attention (tf32 mma, 128-row q tiles) -> y
    {
        dim3 grid(TT / 128, HH, BB);
        attn_mma_kernel<<<grid, 256, ATTN_SMEM_BYTES>>>(qkv, y);
    }

    // 3) out = y @ w_proj + b_proj   [8192, 1024]
    {
        dim3 grid(CC / 128, M / 128);
        gemm_tf32_kernel<<<grid, 256, GEMM_SMEM_BYTES>>>(y, w_proj, b_proj, out, M, CC, CC);
    }
}